// round 9
// baseline (speedup 1.0000x reference)
#include <cuda_runtime.h>
#include <cuda_bf16.h>
#include <cuda.h>
#include <cstdint>

// ---------------- problem dims ----------------
static constexpr int TOKENS = 8192;   // M
static constexpr int IN_F   = 4096;   // K
static constexpr int OUT_F  = 4096;   // N

static constexpr int TM = 128;
static constexpr int TN = 256;
static constexpr int TK = 64;
static constexpr int STAGES  = 3;
static constexpr int K_ITERS = IN_F / TK;     // 64
static constexpr int N_TILES = OUT_F / TN;    // 16
static constexpr int M_TILES = TOKENS / TM;   // 64

static constexpr int N_COMPUTE_WARPS = 16;    // 512 compute threads
static constexpr int BLOCK_THREADS   = 544;   // + 1 producer warp

// ---------------- SMEM layout (dynamic) ----------------
static constexpr int SMEM_MBAR   = 16;        // full(s)=16+s*16, empty(s)=+8
static constexpr int SMEM_DATA   = 1024;      // 1024-aligned (SW128 atoms)
static constexpr int A_BYTES     = TM * TK * 2;           // 16384 (one limb)
static constexpr int B_BYTES     = TN * TK * 2;           // 32768
static constexpr int STAGE_BYTES = 2 * A_BYTES + B_BYTES; // 65536
static constexpr int SMEM_TOTAL  = SMEM_DATA + STAGES * STAGE_BYTES; // 197632

// ---------------- scratch (device globals: no allocs allowed) ----------------
__device__ __nv_bfloat16 g_Ahi[(size_t)TOKENS * IN_F];  // 64 MB
__device__ __nv_bfloat16 g_Alo[(size_t)TOKENS * IN_F];  // 64 MB
__device__ __nv_bfloat16 g_Bq [(size_t)OUT_F  * IN_F];  // 32 MB (ternary, exact in bf16)
__device__ int           g_nnz = 0;   // 1 iff any quantized weight != 0

// ---------------- PTX helpers (base-target instructions ONLY) ----------------
__device__ __forceinline__ uint32_t smem_u32(const void* p) {
    uint32_t a;
    asm("{ .reg .u64 t; cvta.to.shared.u64 t, %1; cvt.u32.u64 %0, t; }" : "=r"(a) : "l"(p));
    return a;
}

#define MBARRIER_INIT(addr, cnt) \
    asm volatile("mbarrier.init.shared.b64 [%0], %1;" :: "r"((uint32_t)(addr)), "r"((uint32_t)(cnt)) : "memory")

#define MBARRIER_ARRIVE(addr) \
    asm volatile("mbarrier.arrive.shared.b64 _, [%0];" :: "r"((uint32_t)(addr)) : "memory")

#define MBARRIER_EXPECT_TX(addr, bytes) \
    asm volatile("mbarrier.arrive.expect_tx.shared.b64 _, [%0], %1;" \
                 :: "r"((uint32_t)(addr)), "r"((uint32_t)(bytes)) : "memory")

#define MBARRIER_WAIT_PARITY(addr, parity) do {                                   \
    uint32_t _mbar = (uint32_t)(addr);                                            \
    uint32_t _par  = (uint32_t)(parity);                                          \
    uint32_t _done;                                                               \
    asm volatile("{\n\t.reg .pred p;\n\t"                                         \
        "mbarrier.try_wait.parity.acquire.cta.shared::cta.b64 p, [%1], %2;\n\t"   \
        "selp.b32 %0, 1, 0, p;\n\t}"                                              \
        : "=r"(_done) : "r"(_mbar), "r"(_par) : "memory");                        \
    if (!_done) {                                                                 \
        asm volatile("{\n\t.reg .pred P1;\n\t"                                    \
            "WAIT_LOOP_%=:\n\t"                                                   \
            "mbarrier.try_wait.parity.acquire.cta.shared::cta.b64 P1, [%0], %1, 0x989680;\n\t" \
            "@P1 bra.uni WAIT_DONE_%=;\n\t"                                       \
            "bra.uni WAIT_LOOP_%=;\n\t"                                           \
            "WAIT_DONE_%=:\n\t}"                                                  \
            :: "r"(_mbar), "r"(_par) : "memory");                                 \
    }                                                                             \
} while (0)

__device__ __forceinline__ void tma_load_2d(uint32_t smem_addr, const void* tmap,
                                            int cx, int cy, uint32_t mbar) {
    asm volatile(
        "cp.async.bulk.tensor.2d.shared::cta.global.tile.mbarrier::complete_tx::bytes "
        "[%0], [%1, {%2, %3}], [%4];"
        :: "r"(smem_addr), "l"(tmap), "r"(cx), "r"(cy), "r"(mbar) : "memory");
}

__device__ __forceinline__ void ldsm_x4(uint32_t* r, uint32_t addr) {
    asm volatile("ldmatrix.sync.aligned.m8n8.x4.shared.b16 {%0,%1,%2,%3}, [%4];"
                 : "=r"(r[0]), "=r"(r[1]), "=r"(r[2]), "=r"(r[3]) : "r"(addr));
}

__device__ __forceinline__ void mma_16816(float* c, const uint32_t* a,
                                          uint32_t b0, uint32_t b1) {
    asm volatile(
        "mma.sync.aligned.m16n8k16.row.col.f32.bf16.bf16.f32 "
        "{%0,%1,%2,%3}, {%4,%5,%6,%7}, {%8,%9}, {%0,%1,%2,%3};"
        : "+f"(c[0]), "+f"(c[1]), "+f"(c[2]), "+f"(c[3])
        : "r"(a[0]), "r"(a[1]), "r"(a[2]), "r"(a[3]), "r"(b0), "r"(b1));
}

// ---------------- shared quantization logic (single definition!) ----------------
__device__ __forceinline__ float quantize_one(float w, float a, int bw) {
    float wc = w / a;
    wc = fminf(1.0f, fmaxf(-1.0f, wc));
    if (bw == 1) return (wc < 0.0f) ? -1.0f : 1.0f;      // sign(0) -> +1
    if (fabsf(wc) < 0.5f) return 0.0f;                    // bw == 2
    return (wc > 0.0f) ? 1.0f : -1.0f;
}

__device__ __forceinline__ int decode_bw(const int* bw_p) {
    int bw = 2;
    if (bw_p) {
        int raw = *bw_p;
        if (raw == 1 || raw == 2) bw = raw;
        else { float f = __int_as_float(raw); int b = (int)f; if (b == 1 || b == 2) bw = b; }
    }
    return bw;
}

// ---------------- kernels ----------------
__global__ void reset_flag_kernel() { g_nnz = 0; }

// Pass 1: detection only (read-only over W). Uses the identical quantize_one
// path so scan and materialization can never disagree.
__global__ void __launch_bounds__(256)
scan_w_kernel(const float4* __restrict__ w4,
              const float* __restrict__ alpha_p,
              const int* __restrict__ bw_p) {
    const float a = fabsf(*alpha_p) + 1e-8f;
    const int bw  = decode_bw(bw_p);
    const size_t n4 = (size_t)OUT_F * IN_F / 4;
    bool nz = false;
    for (size_t i = (size_t)blockIdx.x * blockDim.x + threadIdx.x; i < n4;
         i += (size_t)gridDim.x * blockDim.x) {
        float4 w = w4[i];
        nz |= (quantize_one(w.x, a, bw) != 0.0f);
        nz |= (quantize_one(w.y, a, bw) != 0.0f);
        nz |= (quantize_one(w.z, a, bw) != 0.0f);
        nz |= (quantize_one(w.w, a, bw) != 0.0f);
    }
    unsigned m = __ballot_sync(0xffffffffu, nz);
    if (m != 0u && (threadIdx.x & 31) == 0) atomicOr(&g_nnz, 1);
}

// Unconditional: out = bias broadcast. The dense GEMM (when nnz!=0) fully
// overwrites the output afterwards, so this is always correct.
__global__ void __launch_bounds__(512)
bias_fill_kernel(const float4* __restrict__ bias4, float4* __restrict__ out4) {
    const size_t n4 = (size_t)TOKENS * OUT_F / 4;   // 8.4M float4
    const size_t stride = (size_t)gridDim.x * blockDim.x;
    for (size_t i = (size_t)blockIdx.x * blockDim.x + threadIdx.x; i < n4;
         i += stride) {
        out4[i] = __ldg(bias4 + (i & (OUT_F / 4 - 1)));
    }
}

// Pass 2 (dense path only): materialize g_Bq + split x into hi/lo bf16 limbs.
static constexpr int QW_BLOCKS = (OUT_F * IN_F / 4) / 256;   // 16384
static constexpr int SX_BLOCKS = 2048;
__global__ void __launch_bounds__(256)
prep_kernel(const float4* __restrict__ w4, const float4* __restrict__ x4,
            const float* __restrict__ alpha_p, const int* __restrict__ bw_p) {
    if (*(volatile int*)&g_nnz == 0) return;        // all-zero: GEMM skipped
    if (blockIdx.x < QW_BLOCKS) {
        const float a = fabsf(*alpha_p) + 1e-8f;
        const int bw  = decode_bw(bw_p);
        size_t i = (size_t)blockIdx.x * 256 + threadIdx.x;
        float4 w = w4[i];
        __nv_bfloat162 p0, p1;
        p0.x = __float2bfloat16(quantize_one(w.x, a, bw));
        p0.y = __float2bfloat16(quantize_one(w.y, a, bw));
        p1.x = __float2bfloat16(quantize_one(w.z, a, bw));
        p1.y = __float2bfloat16(quantize_one(w.w, a, bw));
        reinterpret_cast<__nv_bfloat162*>(g_Bq)[2 * i]     = p0;
        reinterpret_cast<__nv_bfloat162*>(g_Bq)[2 * i + 1] = p1;
    } else {
        const size_t n4 = (size_t)TOKENS * IN_F / 4;
        for (size_t i = (size_t)(blockIdx.x - QW_BLOCKS) * 256 + threadIdx.x;
             i < n4; i += (size_t)SX_BLOCKS * 256) {
            float4 v = x4[i];
            __nv_bfloat16 h0 = __float2bfloat16(v.x);
            __nv_bfloat16 h1 = __float2bfloat16(v.y);
            __nv_bfloat16 h2 = __float2bfloat16(v.z);
            __nv_bfloat16 h3 = __float2bfloat16(v.w);
            __nv_bfloat162 hi0, hi1, lo0, lo1;
            hi0.x = h0; hi0.y = h1; hi1.x = h2; hi1.y = h3;
            lo0.x = __float2bfloat16(v.x - __bfloat162float(h0));
            lo0.y = __float2bfloat16(v.y - __bfloat162float(h1));
            lo1.x = __float2bfloat16(v.z - __bfloat162float(h2));
            lo1.y = __float2bfloat16(v.w - __bfloat162float(h3));
            reinterpret_cast<__nv_bfloat162*>(g_Ahi)[2 * i]     = hi0;
            reinterpret_cast<__nv_bfloat162*>(g_Ahi)[2 * i + 1] = hi1;
            reinterpret_cast<__nv_bfloat162*>(g_Alo)[2 * i]     = lo0;
            reinterpret_cast<__nv_bfloat162*>(g_Alo)[2 * i + 1] = lo1;
        }
    }
}

// ---------------- main GEMM (dense path; early-exits when nnz==0) ----------------
// D = (Ahi + Alo) @ Bq^T ; out = alpha*D + bias
// CTA tile 128x256, 16 compute warps (warp tile 32m x 64n) + 1 TMA producer warp.
// SMEM SW128 swizzle: phys = row*128 + (colbytes ^ ((row&7)<<4)).
__global__ void __launch_bounds__(BLOCK_THREADS, 1)
gemm_kernel(const __grid_constant__ CUtensorMap tmap_ahi,
            const __grid_constant__ CUtensorMap tmap_alo,
            const __grid_constant__ CUtensorMap tmap_b,
            const float* __restrict__ alpha_p,
            const float* __restrict__ bias,
            float* __restrict__ out) {
    if (*(volatile int*)&g_nnz == 0) return;    // bias_fill already wrote output

    extern __shared__ char smem[];
    const uint32_t sb = smem_u32(smem);
    const int tid  = threadIdx.x;
    const int lane = tid & 31;
    const int wid  = tid >> 5;

    const int nt = blockIdx.x & (N_TILES - 1);
    const int mt = blockIdx.x >> 4;

    if (tid == 0) {
        for (int s = 0; s < STAGES; s++) {
            MBARRIER_INIT(sb + SMEM_MBAR + s * 16,     1);                // full: tx-based
            MBARRIER_INIT(sb + SMEM_MBAR + s * 16 + 8, N_COMPUTE_WARPS); // empty
        }
    }
    __syncthreads();

    if (wid == N_COMPUTE_WARPS) {
        // ---------------- producer warp (1 thread) ----------------
        if (lane == 0) {
            int s = 0, ph = 1;   // first empty-wait passes immediately
            for (int it = 0; it < K_ITERS; ++it) {
                MBARRIER_WAIT_PARITY(sb + SMEM_MBAR + s * 16 + 8, ph);
                const uint32_t full = sb + SMEM_MBAR + s * 16;
                MBARRIER_EXPECT_TX(full, STAGE_BYTES);
                const uint32_t base = sb + SMEM_DATA + s * STAGE_BYTES;
                tma_load_2d(base,               &tmap_ahi, it * TK, mt * TM, full);
                tma_load_2d(base + A_BYTES,     &tmap_alo, it * TK, mt * TM, full);
                tma_load_2d(base + 2 * A_BYTES, &tmap_b,   it * TK, nt * TN, full);
                if (++s == STAGES) { s = 0; ph ^= 1; }
            }
        }
    } else {
        // ---------------- compute warps ----------------
        const int wm = wid & 3;          // 0..3 -> m offset wm*32
        const int wn = wid >> 2;         // 0..3 -> n offset wn*64

        const int rA  = wm * 32 + (lane & 15);
        const int cA2 = (lane >> 4) * 16;
        const int xA  = (rA & 7) << 4;
        const int rB  = wn * 64 + ((lane >> 4) << 3) + (lane & 7);
        const int cB2 = ((lane >> 3) & 1) * 16;
        const int xB  = (rB & 7) << 4;

        float acc[2][8][4];
#pragma unroll
        for (int i = 0; i < 2; i++)
#pragma unroll
            for (int j = 0; j < 8; j++)
#pragma unroll
                for (int e = 0; e < 4; e++) acc[i][j][e] = 0.0f;

        int s = 0, ph = 0;
        for (int it = 0; it < K_ITERS; ++it) {
            MBARRIER_WAIT_PARITY(sb + SMEM_MBAR + s * 16, ph);
            const uint32_t stage = sb + SMEM_DATA + s * STAGE_BYTES;
            const uint32_t aHi = stage + rA * 128;
            const uint32_t aLo = aHi + A_BYTES;
            const uint32_t bBs = stage + 2 * A_BYTES + rB * 128;

#pragma unroll
            for (int k16 = 0; k16 < TK / 16; ++k16) {
                const uint32_t swa = (uint32_t)((k16 * 32 + cA2) ^ xA);
                const uint32_t swb = (uint32_t)((k16 * 32 + cB2) ^ xB);

                uint32_t b[4][4];
#pragma unroll
                for (int j = 0; j < 4; j++)          // 4 x (16n x 16k)
                    ldsm_x4(b[j], bBs + j * 2048 + swb);

                uint32_t a0[4], a1[4];
                ldsm_x4(a0, aHi + swa);              // m frag 0 (hi limb)
                ldsm_x4(a1, aHi + 2048 + swa);       // m frag 1
#pragma unroll
                for (int j = 0; j < 4; j++) {
#pragma unroll
                    for (int h = 0; h < 2; h++) {
                        mma_16816(acc[0][j * 2 + h], a0, b[j][h * 2], b[j][h * 2 + 1]);
                        mma_16816(acc[1][j * 2 + h], a1, b[j][h * 2], b[j][h * 2 + 1]);
                    }
                }

                ldsm_x4(a0, aLo + swa);              // lo limb, reuse B regs
                ldsm_x4(a1, aLo + 2048 + swa);
#pragma unroll
                for (int j = 0; j < 4; j++) {
#pragma unroll
                    for (int h = 0; h < 2; h++) {
                        mma_16816(acc[0][j * 2 + h], a0, b[j][h * 2], b[j][h * 2 + 1]);
                        mma_16816(acc[1][j * 2 + h], a1, b[j][h * 2], b[j][h * 2 + 1]);
                    }
                }
            }
            if (lane == 0) MBARRIER_ARRIVE(sb + SMEM_MBAR + s * 16 + 8);
            if (++s == STAGES) { s = 0; ph ^= 1; }
        }

        // ---------------- epilogue: out = alpha*acc + bias ----------------
        const float aeff = fabsf(*alpha_p) + 1e-8f;
        const int r0 = mt * TM + wm * 32 + (lane >> 2);
        const int c0 = nt * TN + wn * 64 + (lane & 3) * 2;
#pragma unroll
        for (int fn = 0; fn < 8; ++fn) {
            const int c = c0 + fn * 8;
            const float2 bv = *reinterpret_cast<const float2*>(bias + c);
#pragma unroll
            for (int fm = 0; fm < 2; ++fm) {
                const int r = r0 + fm * 16;
                float2 o0, o1;
                o0.x = fmaf(aeff, acc[fm][fn][0], bv.x);
                o0.y = fmaf(aeff, acc[fm][fn][1], bv.y);
                o1.x = fmaf(aeff, acc[fm][fn][2], bv.x);
                o1.y = fmaf(aeff, acc[fm][fn][3], bv.y);
                *reinterpret_cast<float2*>(out + (size_t)r * OUT_F + c)       = o0;
                *reinterpret_cast<float2*>(out + (size_t)(r + 8) * OUT_F + c) = o1;
            }
        }
    }
}

// ---------------- host launcher ----------------
typedef CUresult (*encode_fn_t)(
    CUtensorMap*, CUtensorMapDataType, cuuint32_t, void*,
    const cuuint64_t*, const cuuint64_t*, const cuuint32_t*, const cuuint32_t*,
    CUtensorMapInterleave, CUtensorMapSwizzle, CUtensorMapL2promotion,
    CUtensorMapFloatOOBfill);

static void encode_2d(encode_fn_t enc, CUtensorMap* tm, void* ptr,
                      int rows, int cols, int box_x, int box_y) {
    cuuint64_t dims[2]    = {(cuuint64_t)cols, (cuuint64_t)rows};
    cuuint64_t strides[1] = {(cuuint64_t)cols * 2};
    cuuint32_t box[2]     = {(cuuint32_t)box_x, (cuuint32_t)box_y};
    cuuint32_t es[2]      = {1, 1};
    enc(tm, CU_TENSOR_MAP_DATA_TYPE_BFLOAT16, 2, ptr, dims, strides, box, es,
        CU_TENSOR_MAP_INTERLEAVE_NONE, CU_TENSOR_MAP_SWIZZLE_128B,
        CU_TENSOR_MAP_L2_PROMOTION_L2_128B, CU_TENSOR_MAP_FLOAT_OOB_FILL_NONE);
}

extern "C" void kernel_launch(void* const* d_in, const int* in_sizes, int n_in,
                              void* d_out, int out_size) {
    const float* x     = (const float*)d_in[0];
    const float* w     = (const float*)d_in[1];
    const float* alpha = (const float*)d_in[2];
    const float* bias  = (const float*)d_in[3];
    const int*   bw    = (n_in >= 5) ? (const int*)d_in[4] : nullptr;
    float* out = (float*)d_out;

    void *ahi = nullptr, *alo = nullptr, *bq = nullptr;
    cudaGetSymbolAddress(&ahi, g_Ahi);
    cudaGetSymbolAddress(&alo, g_Alo);
    cudaGetSymbolAddress(&bq,  g_Bq);

    encode_fn_t enc = nullptr;
    {
        void* fn = nullptr;
        cudaDriverEntryPointQueryResult st;
        cudaGetDriverEntryPointByVersion("cuTensorMapEncodeTiled", &fn, 12000,
                                         cudaEnableDefault, &st);
        enc = (encode_fn_t)fn;
    }

    CUtensorMap tm_ahi{}, tm_alo{}, tm_b{};
    encode_2d(enc, &tm_ahi, ahi, TOKENS, IN_F, TK, TM);
    encode_2d(enc, &tm_alo, alo, TOKENS, IN_F, TK, TM);
    encode_2d(enc, &tm_b,   bq,  OUT_F,  IN_F, TK, TN);

    reset_flag_kernel<<<1, 1>>>();
    scan_w_kernel<<<2048, 256>>>((const float4*)w, alpha, bw);
    bias_fill_kernel<<<2048, 512>>>((const float4*)bias, (float4*)out);
    prep_kernel<<<QW_BLOCKS + SX_BLOCKS, 256>>>(
        (const float4*)w, (const float4*)x, alpha, bw);

    cudaFuncSetAttribute(gemm_kernel, cudaFuncAttributeMaxDynamicSharedMemorySize,
                         SMEM_TOTAL);
    gemm_kernel<<<M_TILES * N_TILES, BLOCK_THREADS, SMEM_TOTAL>>>(
        tm_ahi, tm_alo, tm_b, alpha, bias, out);
}

// round 10
// speedup vs baseline: 1.7210x; 1.7210x over previous
#include <cuda_runtime.h>
#include <cuda_bf16.h>
#include <cuda.h>
#include <cstdint>

// ---------------- problem dims ----------------
static constexpr int TOKENS = 8192;   // M
static constexpr int IN_F   = 4096;   // K
static constexpr int OUT_F  = 4096;   // N

static constexpr int TM = 128;
static constexpr int TN = 256;
static constexpr int TK = 64;
static constexpr int STAGES  = 3;
static constexpr int K_ITERS = IN_F / TK;     // 64
static constexpr int N_TILES = OUT_F / TN;    // 16
static constexpr int M_TILES = TOKENS / TM;   // 64
static constexpr int TILES   = M_TILES * N_TILES;  // 1024

static constexpr int N_COMPUTE_WARPS = 16;    // 512 compute threads
static constexpr int BLOCK_THREADS   = 544;   // + 1 producer warp
static constexpr int GEMM_GRID       = 148;   // persistent: one wave

static constexpr int SCAN_BLOCKS = 1184;      // = 148 * 8
static constexpr int FILL_BLOCKS = 1184;

// ---------------- SMEM layout (dynamic) ----------------
static constexpr int SMEM_MBAR   = 16;        // full(s)=16+s*16, empty(s)=+8
static constexpr int SMEM_DATA   = 1024;      // 1024-aligned (SW128 atoms)
static constexpr int A_BYTES     = TM * TK * 2;           // 16384 (one limb)
static constexpr int B_BYTES     = TN * TK * 2;           // 32768
static constexpr int STAGE_BYTES = 2 * A_BYTES + B_BYTES; // 65536
static constexpr int SMEM_TOTAL  = SMEM_DATA + STAGES * STAGE_BYTES; // 197632

// ---------------- scratch (device globals: no allocs allowed) ----------------
__device__ __nv_bfloat16 g_Ahi[(size_t)TOKENS * IN_F];  // 64 MB
__device__ __nv_bfloat16 g_Alo[(size_t)TOKENS * IN_F];  // 64 MB
__device__ __nv_bfloat16 g_Bq [(size_t)OUT_F  * IN_F];  // 32 MB (ternary, exact in bf16)
__device__ int g_partial[SCAN_BLOCKS];   // per-block nz flags (written unconditionally)
__device__ int g_nnz;                    // republished by fill_or_prep block 0

// ---------------- PTX helpers (base-target instructions ONLY) ----------------
__device__ __forceinline__ uint32_t smem_u32(const void* p) {
    uint32_t a;
    asm("{ .reg .u64 t; cvta.to.shared.u64 t, %1; cvt.u32.u64 %0, t; }" : "=r"(a) : "l"(p));
    return a;
}

#define MBARRIER_INIT(addr, cnt) \
    asm volatile("mbarrier.init.shared.b64 [%0], %1;" :: "r"((uint32_t)(addr)), "r"((uint32_t)(cnt)) : "memory")

#define MBARRIER_ARRIVE(addr) \
    asm volatile("mbarrier.arrive.shared.b64 _, [%0];" :: "r"((uint32_t)(addr)) : "memory")

#define MBARRIER_EXPECT_TX(addr, bytes) \
    asm volatile("mbarrier.arrive.expect_tx.shared.b64 _, [%0], %1;" \
                 :: "r"((uint32_t)(addr)), "r"((uint32_t)(bytes)) : "memory")

#define MBARRIER_WAIT_PARITY(addr, parity) do {                                   \
    uint32_t _mbar = (uint32_t)(addr);                                            \
    uint32_t _par  = (uint32_t)(parity);                                          \
    uint32_t _done;                                                               \
    asm volatile("{\n\t.reg .pred p;\n\t"                                         \
        "mbarrier.try_wait.parity.acquire.cta.shared::cta.b64 p, [%1], %2;\n\t"   \
        "selp.b32 %0, 1, 0, p;\n\t}"                                              \
        : "=r"(_done) : "r"(_mbar), "r"(_par) : "memory");                        \
    if (!_done) {                                                                 \
        asm volatile("{\n\t.reg .pred P1;\n\t"                                    \
            "WAIT_LOOP_%=:\n\t"                                                   \
            "mbarrier.try_wait.parity.acquire.cta.shared::cta.b64 P1, [%0], %1, 0x989680;\n\t" \
            "@P1 bra.uni WAIT_DONE_%=;\n\t"                                       \
            "bra.uni WAIT_LOOP_%=;\n\t"                                           \
            "WAIT_DONE_%=:\n\t}"                                                  \
            :: "r"(_mbar), "r"(_par) : "memory");                                 \
    }                                                                             \
} while (0)

__device__ __forceinline__ void tma_load_2d(uint32_t smem_addr, const void* tmap,
                                            int cx, int cy, uint32_t mbar) {
    asm volatile(
        "cp.async.bulk.tensor.2d.shared::cta.global.tile.mbarrier::complete_tx::bytes "
        "[%0], [%1, {%2, %3}], [%4];"
        :: "r"(smem_addr), "l"(tmap), "r"(cx), "r"(cy), "r"(mbar) : "memory");
}

__device__ __forceinline__ void ldsm_x4(uint32_t* r, uint32_t addr) {
    asm volatile("ldmatrix.sync.aligned.m8n8.x4.shared.b16 {%0,%1,%2,%3}, [%4];"
                 : "=r"(r[0]), "=r"(r[1]), "=r"(r[2]), "=r"(r[3]) : "r"(addr));
}

__device__ __forceinline__ void mma_16816(float* c, const uint32_t* a,
                                          uint32_t b0, uint32_t b1) {
    asm volatile(
        "mma.sync.aligned.m16n8k16.row.col.f32.bf16.bf16.f32 "
        "{%0,%1,%2,%3}, {%4,%5,%6,%7}, {%8,%9}, {%0,%1,%2,%3};"
        : "+f"(c[0]), "+f"(c[1]), "+f"(c[2]), "+f"(c[3])
        : "r"(a[0]), "r"(a[1]), "r"(a[2]), "r"(a[3]), "r"(b0), "r"(b1));
}

// ---------------- shared quantization logic (single definition!) ----------------
__device__ __forceinline__ float quantize_one(float w, float a, int bw) {
    float wc = w / a;
    wc = fminf(1.0f, fmaxf(-1.0f, wc));
    if (bw == 1) return (wc < 0.0f) ? -1.0f : 1.0f;      // sign(0) -> +1
    if (fabsf(wc) < 0.5f) return 0.0f;                    // bw == 2
    return (wc > 0.0f) ? 1.0f : -1.0f;
}

__device__ __forceinline__ int decode_bw(const int* bw_p) {
    int bw = 2;
    if (bw_p) {
        int raw = *bw_p;
        if (raw == 1 || raw == 2) bw = raw;
        else { float f = __int_as_float(raw); int b = (int)f; if (b == 1 || b == 2) bw = b; }
    }
    return bw;
}

// ---------------- kernel 1: scan W, write per-block partial flags ----------------
// Every block writes its slot unconditionally -> no reset kernel, no stale state.
__global__ void __launch_bounds__(256)
scan_w_kernel(const float4* __restrict__ w4,
              const float* __restrict__ alpha_p,
              const int* __restrict__ bw_p) {
    const float a = fabsf(*alpha_p) + 1e-8f;
    const int bw  = decode_bw(bw_p);
    const size_t n4 = (size_t)OUT_F * IN_F / 4;
    bool nz = false;
    for (size_t i = (size_t)blockIdx.x * blockDim.x + threadIdx.x; i < n4;
         i += (size_t)gridDim.x * blockDim.x) {
        float4 w = w4[i];
        nz |= (quantize_one(w.x, a, bw) != 0.0f);
        nz |= (quantize_one(w.y, a, bw) != 0.0f);
        nz |= (quantize_one(w.z, a, bw) != 0.0f);
        nz |= (quantize_one(w.w, a, bw) != 0.0f);
    }
    int any = __syncthreads_or(nz ? 1 : 0);
    if (threadIdx.x == 0) g_partial[blockIdx.x] = any;   // unconditional write
}

// ---------------- kernel 2: fused bias-fill OR dense prep ----------------
// Reduces the partial array per block (spread sectors, no hotspot). Block 0
// republishes the combined flag into g_nnz for the GEMM kernel.
__global__ void __launch_bounds__(512)
fill_or_prep_kernel(const float4* __restrict__ w4, const float4* __restrict__ x4,
                    const float* __restrict__ alpha_p, const int* __restrict__ bw_p,
                    const float4* __restrict__ bias4, float4* __restrict__ out4) {
    int mine = 0;
    for (int i = threadIdx.x; i < SCAN_BLOCKS; i += 512) mine |= g_partial[i];
    const int nnz = __syncthreads_or(mine);
    if (blockIdx.x == 0 && threadIdx.x == 0) g_nnz = nnz;  // unconditional republish

    const size_t stride = (size_t)gridDim.x * blockDim.x;
    const size_t tid0   = (size_t)blockIdx.x * blockDim.x + threadIdx.x;

    if (nnz == 0) {
        // all quantized weights are zero: out = bias broadcast (GEMM will exit)
        const size_t n4 = (size_t)TOKENS * OUT_F / 4;
        for (size_t i = tid0; i < n4; i += stride)
            out4[i] = __ldg(bias4 + (i & (OUT_F / 4 - 1)));
    } else {
        // dense path: materialize ternary Bq and split x into hi/lo bf16 limbs
        const float a = fabsf(*alpha_p) + 1e-8f;
        const int bw  = decode_bw(bw_p);
        const size_t nw4 = (size_t)OUT_F * IN_F / 4;
        for (size_t i = tid0; i < nw4; i += stride) {
            float4 w = w4[i];
            __nv_bfloat162 p0, p1;
            p0.x = __float2bfloat16(quantize_one(w.x, a, bw));
            p0.y = __float2bfloat16(quantize_one(w.y, a, bw));
            p1.x = __float2bfloat16(quantize_one(w.z, a, bw));
            p1.y = __float2bfloat16(quantize_one(w.w, a, bw));
            reinterpret_cast<__nv_bfloat162*>(g_Bq)[2 * i]     = p0;
            reinterpret_cast<__nv_bfloat162*>(g_Bq)[2 * i + 1] = p1;
        }
        const size_t nx4 = (size_t)TOKENS * IN_F / 4;
        for (size_t i = tid0; i < nx4; i += stride) {
            float4 v = x4[i];
            __nv_bfloat16 h0 = __float2bfloat16(v.x);
            __nv_bfloat16 h1 = __float2bfloat16(v.y);
            __nv_bfloat16 h2 = __float2bfloat16(v.z);
            __nv_bfloat16 h3 = __float2bfloat16(v.w);
            __nv_bfloat162 hi0, hi1, lo0, lo1;
            hi0.x = h0; hi0.y = h1; hi1.x = h2; hi1.y = h3;
            lo0.x = __float2bfloat16(v.x - __bfloat162float(h0));
            lo0.y = __float2bfloat16(v.y - __bfloat162float(h1));
            lo1.x = __float2bfloat16(v.z - __bfloat162float(h2));
            lo1.y = __float2bfloat16(v.w - __bfloat162float(h3));
            reinterpret_cast<__nv_bfloat162*>(g_Ahi)[2 * i]     = hi0;
            reinterpret_cast<__nv_bfloat162*>(g_Ahi)[2 * i + 1] = hi1;
            reinterpret_cast<__nv_bfloat162*>(g_Alo)[2 * i]     = lo0;
            reinterpret_cast<__nv_bfloat162*>(g_Alo)[2 * i + 1] = lo1;
        }
    }
}

// ---------------- kernel 3: persistent GEMM (dense path only) ----------------
// D = (Ahi + Alo) @ Bq^T ; out = alpha*D + bias
// Grid = 148 (one wave). Each CTA loops over tiles bid, bid+148, ...
// Early exit when nnz==0 costs one wave + one flag load per block.
// SMEM SW128 swizzle: phys = row*128 + (colbytes ^ ((row&7)<<4)).
__global__ void __launch_bounds__(BLOCK_THREADS, 1)
gemm_kernel(const __grid_constant__ CUtensorMap tmap_ahi,
            const __grid_constant__ CUtensorMap tmap_alo,
            const __grid_constant__ CUtensorMap tmap_b,
            const float* __restrict__ alpha_p,
            const float* __restrict__ bias,
            float* __restrict__ out) {
    __shared__ int sflag;
    if (threadIdx.x == 0) sflag = g_nnz;    // ONE load per block
    __syncthreads();
    if (sflag == 0) return;                 // fill_or_prep already wrote output

    extern __shared__ char smem[];
    const uint32_t sb = smem_u32(smem);
    const int tid  = threadIdx.x;
    const int lane = tid & 31;
    const int wid  = tid >> 5;

    if (tid == 0) {
        for (int s = 0; s < STAGES; s++) {
            MBARRIER_INIT(sb + SMEM_MBAR + s * 16,     1);                // full: tx-based
            MBARRIER_INIT(sb + SMEM_MBAR + s * 16 + 8, N_COMPUTE_WARPS); // empty
        }
    }
    __syncthreads();

    if (wid == N_COMPUTE_WARPS) {
        // ---------------- producer warp (1 thread), persistent over tiles ----------------
        if (lane == 0) {
            int s = 0, ph = 1;   // first empty-wait passes immediately
            for (int t = blockIdx.x; t < TILES; t += gridDim.x) {
                const int mt = t >> 4, nt = t & (N_TILES - 1);
                for (int it = 0; it < K_ITERS; ++it) {
                    MBARRIER_WAIT_PARITY(sb + SMEM_MBAR + s * 16 + 8, ph);
                    const uint32_t full = sb + SMEM_MBAR + s * 16;
                    MBARRIER_EXPECT_TX(full, STAGE_BYTES);
                    const uint32_t base = sb + SMEM_DATA + s * STAGE_BYTES;
                    tma_load_2d(base,               &tmap_ahi, it * TK, mt * TM, full);
                    tma_load_2d(base + A_BYTES,     &tmap_alo, it * TK, mt * TM, full);
                    tma_load_2d(base + 2 * A_BYTES, &tmap_b,   it * TK, nt * TN, full);
                    if (++s == STAGES) { s = 0; ph ^= 1; }
                }
            }
        }
    } else {
        // ---------------- compute warps, persistent over tiles ----------------
        const int wm = wid & 3;          // 0..3 -> m offset wm*32
        const int wn = wid >> 2;         // 0..3 -> n offset wn*64

        const int rA  = wm * 32 + (lane & 15);
        const int cA2 = (lane >> 4) * 16;
        const int xA  = (rA & 7) << 4;
        const int rB  = wn * 64 + ((lane >> 4) << 3) + (lane & 7);
        const int cB2 = ((lane >> 3) & 1) * 16;
        const int xB  = (rB & 7) << 4;

        const float aeff = fabsf(*alpha_p) + 1e-8f;

        int s = 0, ph = 0;
        for (int t = blockIdx.x; t < TILES; t += gridDim.x) {
            const int mt = t >> 4, nt = t & (N_TILES - 1);

            float acc[2][8][4];
#pragma unroll
            for (int i = 0; i < 2; i++)
#pragma unroll
                for (int j = 0; j < 8; j++)
#pragma unroll
                    for (int e = 0; e < 4; e++) acc[i][j][e] = 0.0f;

            for (int it = 0; it < K_ITERS; ++it) {
                MBARRIER_WAIT_PARITY(sb + SMEM_MBAR + s * 16, ph);
                const uint32_t stage = sb + SMEM_DATA + s * STAGE_BYTES;
                const uint32_t aHi = stage + rA * 128;
                const uint32_t aLo = aHi + A_BYTES;
                const uint32_t bBs = stage + 2 * A_BYTES + rB * 128;

#pragma unroll
                for (int k16 = 0; k16 < TK / 16; ++k16) {
                    const uint32_t swa = (uint32_t)((k16 * 32 + cA2) ^ xA);
                    const uint32_t swb = (uint32_t)((k16 * 32 + cB2) ^ xB);

                    uint32_t b[4][4];
#pragma unroll
                    for (int j = 0; j < 4; j++)          // 4 x (16n x 16k)
                        ldsm_x4(b[j], bBs + j * 2048 + swb);

                    uint32_t a0[4], a1[4];
                    ldsm_x4(a0, aHi + swa);              // m frag 0 (hi limb)
                    ldsm_x4(a1, aHi + 2048 + swa);       // m frag 1
#pragma unroll
                    for (int j = 0; j < 4; j++) {
#pragma unroll
                        for (int h = 0; h < 2; h++) {
                            mma_16816(acc[0][j * 2 + h], a0, b[j][h * 2], b[j][h * 2 + 1]);
                            mma_16816(acc[1][j * 2 + h], a1, b[j][h * 2], b[j][h * 2 + 1]);
                        }
                    }

                    ldsm_x4(a0, aLo + swa);              // lo limb, reuse B regs
                    ldsm_x4(a1, aLo + 2048 + swa);
#pragma unroll
                    for (int j = 0; j < 4; j++) {
#pragma unroll
                        for (int h = 0; h < 2; h++) {
                            mma_16816(acc[0][j * 2 + h], a0, b[j][h * 2], b[j][h * 2 + 1]);
                            mma_16816(acc[1][j * 2 + h], a1, b[j][h * 2], b[j][h * 2 + 1]);
                        }
                    }
                }
                if (lane == 0) MBARRIER_ARRIVE(sb + SMEM_MBAR + s * 16 + 8);
                if (++s == STAGES) { s = 0; ph ^= 1; }
            }

            // ---------------- epilogue: out = alpha*acc + bias ----------------
            const int r0 = mt * TM + wm * 32 + (lane >> 2);
            const int c0 = nt * TN + wn * 64 + (lane & 3) * 2;
#pragma unroll
            for (int fn = 0; fn < 8; ++fn) {
                const int c = c0 + fn * 8;
                const float2 bv = *reinterpret_cast<const float2*>(bias + c);
#pragma unroll
                for (int fm = 0; fm < 2; ++fm) {
                    const int r = r0 + fm * 16;
                    float2 o0, o1;
                    o0.x = fmaf(aeff, acc[fm][fn][0], bv.x);
                    o0.y = fmaf(aeff, acc[fm][fn][1], bv.y);
                    o1.x = fmaf(aeff, acc[fm][fn][2], bv.x);
                    o1.y = fmaf(aeff, acc[fm][fn][3], bv.y);
                    *reinterpret_cast<float2*>(out + (size_t)r * OUT_F + c)       = o0;
                    *reinterpret_cast<float2*>(out + (size_t)(r + 8) * OUT_F + c) = o1;
                }
            }
        }
    }
}

// ---------------- host launcher ----------------
typedef CUresult (*encode_fn_t)(
    CUtensorMap*, CUtensorMapDataType, cuuint32_t, void*,
    const cuuint64_t*, const cuuint64_t*, const cuuint32_t*, const cuuint32_t*,
    CUtensorMapInterleave, CUtensorMapSwizzle, CUtensorMapL2promotion,
    CUtensorMapFloatOOBfill);

static void encode_2d(encode_fn_t enc, CUtensorMap* tm, void* ptr,
                      int rows, int cols, int box_x, int box_y) {
    cuuint64_t dims[2]    = {(cuuint64_t)cols, (cuuint64_t)rows};
    cuuint64_t strides[1] = {(cuuint64_t)cols * 2};
    cuuint32_t box[2]     = {(cuuint32_t)box_x, (cuuint32_t)box_y};
    cuuint32_t es[2]      = {1, 1};
    enc(tm, CU_TENSOR_MAP_DATA_TYPE_BFLOAT16, 2, ptr, dims, strides, box, es,
        CU_TENSOR_MAP_INTERLEAVE_NONE, CU_TENSOR_MAP_SWIZZLE_128B,
        CU_TENSOR_MAP_L2_PROMOTION_L2_128B, CU_TENSOR_MAP_FLOAT_OOB_FILL_NONE);
}

extern "C" void kernel_launch(void* const* d_in, const int* in_sizes, int n_in,
                              void* d_out, int out_size) {
    const float* x     = (const float*)d_in[0];
    const float* w     = (const float*)d_in[1];
    const float* alpha = (const float*)d_in[2];
    const float* bias  = (const float*)d_in[3];
    const int*   bw    = (n_in >= 5) ? (const int*)d_in[4] : nullptr;
    float* out = (float*)d_out;

    void *ahi = nullptr, *alo = nullptr, *bq = nullptr;
    cudaGetSymbolAddress(&ahi, g_Ahi);
    cudaGetSymbolAddress(&alo, g_Alo);
    cudaGetSymbolAddress(&bq,  g_Bq);

    encode_fn_t enc = nullptr;
    {
        void* fn = nullptr;
        cudaDriverEntryPointQueryResult st;
        cudaGetDriverEntryPointByVersion("cuTensorMapEncodeTiled", &fn, 12000,
                                         cudaEnableDefault, &st);
        enc = (encode_fn_t)fn;
    }

    CUtensorMap tm_ahi{}, tm_alo{}, tm_b{};
    encode_2d(enc, &tm_ahi, ahi, TOKENS, IN_F, TK, TM);
    encode_2d(enc, &tm_alo, alo, TOKENS, IN_F, TK, TM);
    encode_2d(enc, &tm_b,   bq,  OUT_F,  IN_F, TK, TN);

    scan_w_kernel<<<SCAN_BLOCKS, 256>>>((const float4*)w, alpha, bw);
    fill_or_prep_kernel<<<FILL_BLOCKS, 512>>>(
        (const float4*)w, (const float4*)x, alpha, bw,
        (const float4*)bias, (float4*)out);

    cudaFuncSetAttribute(gemm_kernel, cudaFuncAttributeMaxDynamicSharedMemorySize,
                         SMEM_TOTAL);
    gemm_kernel<<<GEMM_GRID, BLOCK_THREADS, SMEM_TOTAL>>>(
        tm_ahi, tm_alo, tm_b, alpha, bias, out);
}